// round 1
// baseline (speedup 1.0000x reference)
#include <cuda_runtime.h>

// Problem constants
#define B_   4
#define T_   3072
#define D_   1024
#define H_   16
#define HD_  64
#define TK_  1025            // 1 + 1024 pooled positions
#define TKPAD 4224           // 4*1025=4100 rounded up to multiple of 128
#define MQ_  (B_ * T_)       // 12288 query rows

// ---------------- scratch (static device globals; no allocation) -------------
__device__ float g_Wc2 [D_ * 3 * D_];      // Wconv permuted (O, KW, I) -> (1024, 3072)
__device__ float g_ktmp[TKPAD * D_];       // pooled K/V input stream, padded rows
__device__ float g_k   [TKPAD * D_];
__device__ float g_v   [TKPAD * D_];
__device__ float g_q   [MQ_ * D_];
__device__ float g_attn[MQ_ * D_];

// ---------------- prep: permute Wconv + copy row0 of each batch --------------
__global__ void prep_kernel(const float* __restrict__ Wconv,
                            const float* __restrict__ x,
                            float* __restrict__ Wc2,
                            float* __restrict__ ktmp) {
    int idx = blockIdx.x * blockDim.x + threadIdx.x;
    const int total = D_ * 3 * D_;   // 3,145,728
    if (idx < total) {
        int o   = idx / (3 * D_);
        int rem = idx - o * (3 * D_);
        int kw  = rem >> 10;          // rem / 1024
        int i   = rem & (D_ - 1);     // rem % 1024
        // Wc2[o][kw][i] = Wconv[o][i][kw]
        Wc2[idx] = Wconv[(size_t)o * 3 * D_ + i * 3 + kw];
    }
    if (idx < B_ * D_) {
        int b = idx >> 10;
        int d = idx & (D_ - 1);
        ktmp[(size_t)(b * TK_) * D_ + d] = x[(size_t)(b * T_) * D_ + d];
    }
}

// ---------------- SGEMM: C = A @ W^T (+bias), optional conv row remap --------
// A: (M, K) row-major.  W: (N, K) row-major.  C: row-major, N columns.
// Tiles: 128x128x16, 256 threads, 8x8 per-thread register tile.
#define BM 128
#define BN 128
#define BK 16
#define TM 8
#define TN 8

__global__ __launch_bounds__(256, 2)
void sgemm_nt(const float* __restrict__ A, const float* __restrict__ W,
              float* __restrict__ C, const float* __restrict__ bias,
              int M, int N, int K, int remap) {
    __shared__ float As[BK][BM];
    __shared__ float Bs[BK][BN];

    const int tid  = threadIdx.x;
    const int row0 = blockIdx.y * BM;
    const int col0 = blockIdx.x * BN;
    const int tx   = tid & 15;   // 0..15 -> N direction
    const int ty   = tid >> 4;   // 0..15 -> M direction

    float acc[TM][TN];
    #pragma unroll
    for (int i = 0; i < TM; i++)
        #pragma unroll
        for (int j = 0; j < TN; j++) acc[i][j] = 0.f;

    for (int k0 = 0; k0 < K; k0 += BK) {
        // Each thread loads 2 float4 of A-tile and 2 float4 of W-tile.
        #pragma unroll
        for (int s = 0; s < 2; s++) {
            int f  = tid + s * 256;       // 0..511
            int r  = f >> 2;              // tile row 0..127
            int kk = (f & 3) * 4;         // 0,4,8,12
            float4 va = *reinterpret_cast<const float4*>(
                &A[(size_t)(row0 + r) * K + k0 + kk]);
            As[kk + 0][r] = va.x; As[kk + 1][r] = va.y;
            As[kk + 2][r] = va.z; As[kk + 3][r] = va.w;
            float4 vb = *reinterpret_cast<const float4*>(
                &W[(size_t)(col0 + r) * K + k0 + kk]);
            Bs[kk + 0][r] = vb.x; Bs[kk + 1][r] = vb.y;
            Bs[kk + 2][r] = vb.z; Bs[kk + 3][r] = vb.w;
        }
        __syncthreads();

        #pragma unroll
        for (int kk = 0; kk < BK; kk++) {
            float ra[TM], rb[TN];
            // vector reads from smem (32B aligned)
            float4 a0 = *reinterpret_cast<const float4*>(&As[kk][ty * TM]);
            float4 a1 = *reinterpret_cast<const float4*>(&As[kk][ty * TM + 4]);
            float4 b0 = *reinterpret_cast<const float4*>(&Bs[kk][tx * TN]);
            float4 b1 = *reinterpret_cast<const float4*>(&Bs[kk][tx * TN + 4]);
            ra[0]=a0.x; ra[1]=a0.y; ra[2]=a0.z; ra[3]=a0.w;
            ra[4]=a1.x; ra[5]=a1.y; ra[6]=a1.z; ra[7]=a1.w;
            rb[0]=b0.x; rb[1]=b0.y; rb[2]=b0.z; rb[3]=b0.w;
            rb[4]=b1.x; rb[5]=b1.y; rb[6]=b1.z; rb[7]=b1.w;
            #pragma unroll
            for (int i = 0; i < TM; i++)
                #pragma unroll
                for (int j = 0; j < TN; j++)
                    acc[i][j] += ra[i] * rb[j];
        }
        __syncthreads();
    }

    #pragma unroll
    for (int i = 0; i < TM; i++) {
        int r = row0 + ty * TM + i;
        int out_r = remap ? (r + (r >> 10) + 1) : r;  // conv rows -> k_tmp rows
        float* crow = C + (size_t)out_r * N + col0 + tx * TN;
        #pragma unroll
        for (int j = 0; j < TN; j += 4) {
            float4 v;
            v.x = acc[i][j + 0]; v.y = acc[i][j + 1];
            v.z = acc[i][j + 2]; v.w = acc[i][j + 3];
            if (bias) {
                int c = col0 + tx * TN + j;
                v.x += bias[c + 0]; v.y += bias[c + 1];
                v.z += bias[c + 2]; v.w += bias[c + 3];
            }
            *reinterpret_cast<float4*>(crow + j) = v;
        }
    }
}

// ---------------- flash-style attention (fp32, online softmax) ---------------
// grid: (T/AQ, B*H); block: 256 threads.
// Mask: attend iff 3*k <= q (ints); key 1024 never attended -> loads in-bounds.
#define AQ 64
#define AK 32
#define AD 64
#define QPAD 68   // float4-aligned padded row stride
#define SPAD 33

__global__ __launch_bounds__(256)
void attn_kernel(const float* __restrict__ Q, const float* __restrict__ Kt,
                 const float* __restrict__ Vt, float* __restrict__ O) {
    __shared__ float Qs[AQ][QPAD];
    __shared__ float Ks[AK][QPAD];
    __shared__ float Vs[AK][QPAD];
    __shared__ float Ss[AQ][SPAD];
    __shared__ float mrow[AQ], lrow[AQ], srow[AQ];

    const int qt = blockIdx.x;
    const int bh = blockIdx.y;
    const int b  = bh >> 4;
    const int h  = bh & 15;
    const int q0 = qt * AQ;

    const int tid = threadIdx.x;
    const int tx  = tid & 15;
    const int ty  = tid >> 4;

    // Load Q tile (rows are (b, q0+r), cols h*64..h*64+63)
    for (int e = tid; e < AQ * AD; e += 256) {
        int r = e >> 6, d = e & 63;
        Qs[r][d] = Q[(size_t)(b * T_ + q0 + r) * D_ + h * HD_ + d];
    }
    if (tid < AQ) { mrow[tid] = -1e30f; lrow[tid] = 0.f; }

    float acc[4][4];
    #pragma unroll
    for (int i = 0; i < 4; i++)
        #pragma unroll
        for (int j = 0; j < 4; j++) acc[i][j] = 0.f;

    const int kmax   = (q0 + AQ - 1) / 3;       // last key any row here attends
    const int ntiles = (kmax + AK) / AK;        // ceil((kmax+1)/AK)

    for (int t = 0; t < ntiles; t++) {
        const int kbase = t * AK;
        __syncthreads();   // protect Ks/Vs/Ss from previous iteration readers
        for (int e = tid; e < AK * AD; e += 256) {
            int r = e >> 6, d = e & 63;
            size_t off = (size_t)(b * TK_ + kbase + r) * D_ + h * HD_ + d;
            Ks[r][d] = Kt[off];
            Vs[r][d] = Vt[off];
        }
        __syncthreads();

        // S = (Q @ K^T) * 1/8, masked.  Thread tile: 4 rows x 2 cols.
        {
            float s[4][2];
            #pragma unroll
            for (int i = 0; i < 4; i++) { s[i][0] = 0.f; s[i][1] = 0.f; }
            const int c0 = tx * 2;
            #pragma unroll
            for (int d4 = 0; d4 < AD / 4; d4++) {
                float4 kv0 = *reinterpret_cast<const float4*>(&Ks[c0 + 0][d4 * 4]);
                float4 kv1 = *reinterpret_cast<const float4*>(&Ks[c0 + 1][d4 * 4]);
                #pragma unroll
                for (int i = 0; i < 4; i++) {
                    float4 qv = *reinterpret_cast<const float4*>(&Qs[ty * 4 + i][d4 * 4]);
                    s[i][0] += qv.x * kv0.x + qv.y * kv0.y + qv.z * kv0.z + qv.w * kv0.w;
                    s[i][1] += qv.x * kv1.x + qv.y * kv1.y + qv.z * kv1.z + qv.w * kv1.w;
                }
            }
            #pragma unroll
            for (int i = 0; i < 4; i++) {
                int qg = q0 + ty * 4 + i;
                #pragma unroll
                for (int j = 0; j < 2; j++) {
                    int kg = kbase + c0 + j;
                    float v = s[i][j] * 0.125f;
                    if (3 * kg > qg) v = -1e30f;   // masked
                    Ss[ty * 4 + i][c0 + j] = v;
                }
            }
        }
        __syncthreads();

        // Online softmax row update (one thread per row)
        if (tid < AQ) {
            int r = tid;
            float m = mrow[r];
            float mn = m;
            #pragma unroll
            for (int c = 0; c < AK; c++) mn = fmaxf(mn, Ss[r][c]);
            float corr = __expf(m - mn);
            float l = lrow[r] * corr;
            #pragma unroll
            for (int c = 0; c < AK; c++) {
                float p = __expf(Ss[r][c] - mn);
                Ss[r][c] = p;
                l += p;
            }
            mrow[r] = mn; lrow[r] = l; srow[r] = corr;
        }
        __syncthreads();

        // O = O*corr + P @ V.  Thread tile: 4 rows x 4 cols.
        #pragma unroll
        for (int i = 0; i < 4; i++) {
            const int r = ty * 4 + i;
            const float corr = srow[r];
            #pragma unroll
            for (int j = 0; j < 4; j++) acc[i][j] *= corr;
            #pragma unroll
            for (int kk = 0; kk < AK; kk++) {
                float p = Ss[r][kk];
                float4 vv = *reinterpret_cast<const float4*>(&Vs[kk][tx * 4]);
                acc[i][0] += p * vv.x;
                acc[i][1] += p * vv.y;
                acc[i][2] += p * vv.z;
                acc[i][3] += p * vv.w;
            }
        }
    }

    // Finalize: divide by l, write (b, t, h*64+hd) layout for the O-proj GEMM
    #pragma unroll
    for (int i = 0; i < 4; i++) {
        int r = ty * 4 + i;
        float inv = 1.f / lrow[r];
        float* orow = O + (size_t)(b * T_ + q0 + r) * D_ + h * HD_ + tx * 4;
        float4 v;
        v.x = acc[i][0] * inv; v.y = acc[i][1] * inv;
        v.z = acc[i][2] * inv; v.w = acc[i][3] * inv;
        *reinterpret_cast<float4*>(orow) = v;
    }
}

// ---------------- launch ------------------------------------------------------
extern "C" void kernel_launch(void* const* d_in, const int* in_sizes, int n_in,
                              void* d_out, int out_size) {
    const float* x     = (const float*)d_in[0];
    const float* Wq    = (const float*)d_in[1];
    const float* Wk    = (const float*)d_in[2];
    const float* Wv    = (const float*)d_in[3];
    const float* Wo    = (const float*)d_in[4];
    const float* bo    = (const float*)d_in[5];
    const float* Wconv = (const float*)d_in[6];
    float* out = (float*)d_out;

    float *Wc2, *ktmp, *k, *v, *q, *attn;
    cudaGetSymbolAddress((void**)&Wc2,  g_Wc2);
    cudaGetSymbolAddress((void**)&ktmp, g_ktmp);
    cudaGetSymbolAddress((void**)&k,    g_k);
    cudaGetSymbolAddress((void**)&v,    g_v);
    cudaGetSymbolAddress((void**)&q,    g_q);
    cudaGetSymbolAddress((void**)&attn, g_attn);

    // 1) permute Wconv, seed k_tmp row 0 per batch
    prep_kernel<<<(D_ * 3 * D_ + 255) / 256, 256>>>(Wconv, x, Wc2, ktmp);

    // 2) conv pooling as GEMM: (4096, 3072) @ Wc2^T -> k_tmp rows (remapped)
    {
        dim3 g(D_ / BN, 4096 / BM);
        sgemm_nt<<<g, 256>>>(x, Wc2, ktmp, nullptr, 4096, D_, 3 * D_, 1);
    }
    // 3) K / V projections over padded rows (junk in pad rows never read)
    {
        dim3 g(D_ / BN, TKPAD / BM);
        sgemm_nt<<<g, 256>>>(ktmp, Wk, k, nullptr, TKPAD, D_, D_, 0);
        sgemm_nt<<<g, 256>>>(ktmp, Wv, v, nullptr, TKPAD, D_, D_, 0);
    }
    // 4) Q projection
    {
        dim3 g(D_ / BN, MQ_ / BM);
        sgemm_nt<<<g, 256>>>(x, Wq, q, nullptr, MQ_, D_, D_, 0);
    }
    // 5) attention
    {
        dim3 g(T_ / AQ, B_ * H_);
        attn_kernel<<<g, 256>>>(q, k, v, attn);
    }
    // 6) output projection + bias -> d_out
    {
        dim3 g(D_ / BN, MQ_ / BM);
        sgemm_nt<<<g, 256>>>(attn, Wo, out, bo, MQ_, D_, D_, 0);
    }
}

// round 7
// speedup vs baseline: 1.9116x; 1.9116x over previous
#include <cuda_runtime.h>
#include <cuda_bf16.h>
#include <cstdint>

// Problem constants
#define B_   4
#define T_   3072
#define D_   1024
#define H_   16
#define HD_  64
#define TK_  1025
#define TKPAD 4224
#define MQ_  (B_ * T_)

typedef __nv_bfloat16 bf16;

// ---------------- scratch (static device globals) ----------------------------
__device__ bf16  g_xhi [MQ_ * D_],  g_xlo [MQ_ * D_];
__device__ bf16  g_Wc2hi[D_ * 3 * D_], g_Wc2lo[D_ * 3 * D_];
__device__ bf16  g_Wqhi[D_ * D_], g_Wqlo[D_ * D_];
__device__ bf16  g_Wkhi[D_ * D_], g_Wklo[D_ * D_];
__device__ bf16  g_Wvhi[D_ * D_], g_Wvlo[D_ * D_];
__device__ bf16  g_Wohi[D_ * D_], g_Wolo[D_ * D_];
__device__ bf16  g_kthi[TKPAD * D_], g_ktlo[TKPAD * D_];
__device__ float g_k   [TKPAD * D_], g_v[TKPAD * D_], g_q[MQ_ * D_];
__device__ bf16  g_athi[MQ_ * D_],  g_atlo[MQ_ * D_];

// ---------------- helpers ----------------------------------------------------
__device__ __forceinline__ uint32_t smem_u32(const void* p) {
    uint32_t a;
    asm("{ .reg .u64 t; cvta.to.shared.u64 t, %1; cvt.u32.u64 %0, t; }"
        : "=r"(a) : "l"(p));
    return a;
}
__device__ __forceinline__ uint32_t swz(uint32_t o) {   // SW128 swizzle
    return o ^ ((o >> 3) & 0x70);
}
__device__ __forceinline__ void split1(float v, bf16& h, bf16& l) {
    h = __float2bfloat16(v);
    l = __float2bfloat16(v - __bfloat162float(h));
}
__device__ __forceinline__ void ldsm4(uint32_t* r, uint32_t a) {
    asm volatile("ldmatrix.sync.aligned.m8n8.x4.shared.b16 {%0,%1,%2,%3}, [%4];"
                 : "=r"(r[0]), "=r"(r[1]), "=r"(r[2]), "=r"(r[3]) : "r"(a));
}
__device__ __forceinline__ void mma16816(float* c, const uint32_t* a, const uint32_t* b) {
    asm volatile(
        "mma.sync.aligned.m16n8k16.row.col.f32.bf16.bf16.f32 "
        "{%0,%1,%2,%3}, {%4,%5,%6,%7}, {%8,%9}, {%0,%1,%2,%3};"
        : "+f"(c[0]), "+f"(c[1]), "+f"(c[2]), "+f"(c[3])
        : "r"(a[0]), "r"(a[1]), "r"(a[2]), "r"(a[3]), "r"(b[0]), "r"(b[1]));
}

// ---------------- pre-pass: elementwise fp32 -> bf16 hi/lo -------------------
__global__ void split_ker(const float* __restrict__ s,
                          bf16* __restrict__ hi, bf16* __restrict__ lo, int n4) {
    int i = blockIdx.x * blockDim.x + threadIdx.x;
    if (i >= n4) return;
    float4 v = reinterpret_cast<const float4*>(s)[i];
    bf16 h0, h1, h2, h3, l0, l1, l2, l3;
    split1(v.x, h0, l0); split1(v.y, h1, l1);
    split1(v.z, h2, l2); split1(v.w, h3, l3);
    reinterpret_cast<__nv_bfloat162*>(hi)[i * 2 + 0] = __halves2bfloat162(h0, h1);
    reinterpret_cast<__nv_bfloat162*>(hi)[i * 2 + 1] = __halves2bfloat162(h2, h3);
    reinterpret_cast<__nv_bfloat162*>(lo)[i * 2 + 0] = __halves2bfloat162(l0, l1);
    reinterpret_cast<__nv_bfloat162*>(lo)[i * 2 + 1] = __halves2bfloat162(l2, l3);
}

// permute Wconv (O,I,KW)->(O,KW,I) + split; seed k_tmp row0/batch; zero pad rows
__global__ void prep_conv(const float* __restrict__ Wconv,
                          const float* __restrict__ x,
                          bf16* __restrict__ Wc2hi, bf16* __restrict__ Wc2lo,
                          bf16* __restrict__ kthi,  bf16* __restrict__ ktlo) {
    int idx = blockIdx.x * blockDim.x + threadIdx.x;
    if (idx < D_ * 3 * D_) {
        int o   = idx / (3 * D_);
        int rem = idx - o * (3 * D_);
        int kw  = rem >> 10;
        int i   = rem & (D_ - 1);
        float v = Wconv[(size_t)o * 3 * D_ + i * 3 + kw];
        bf16 h, l; split1(v, h, l);
        Wc2hi[idx] = h; Wc2lo[idx] = l;
    }
    if (idx < B_ * D_) {
        int b = idx >> 10, d = idx & (D_ - 1);
        float v = x[(size_t)(b * T_) * D_ + d];
        bf16 h, l; split1(v, h, l);
        kthi[(size_t)(b * TK_) * D_ + d] = h;
        ktlo[(size_t)(b * TK_) * D_ + d] = l;
    }
    if (idx < (TKPAD - B_ * TK_) * D_) {
        size_t off = (size_t)(B_ * TK_) * D_ + idx;
        kthi[off] = __float2bfloat16(0.f);
        ktlo[off] = __float2bfloat16(0.f);
    }
}

// ---------------- HMMA split-bf16 GEMM: C = A @ W^T --------------------------
// Block 128x128x64, 256 thr (8 warps, 2x4 grid, warp tile 64x32), cp.async 2-stage.
#define GBM 128
#define GBN 128
#define TILE_B 16384              // 128 rows x 64 bf16 x 2B
#define STAGE_B (4 * TILE_B)      // AH, AL, BH, BL
#define GSMEM (2 * STAGE_B)       // 128 KB

__global__ __launch_bounds__(256, 1)
void gemm_hmma(const bf16* __restrict__ Ahi, const bf16* __restrict__ Alo,
               const bf16* __restrict__ Bhi, const bf16* __restrict__ Blo,
               float* __restrict__ Cf, bf16* __restrict__ Chi, bf16* __restrict__ Clo,
               const float* __restrict__ bias, int M, int N, int K, int remap) {
    extern __shared__ char smem[];
    const uint32_t sb = smem_u32(smem);
    const int tid  = threadIdx.x;
    const int lane = tid & 31;
    const int wid  = tid >> 5;
    const int wm   = wid >> 2;        // 0..1
    const int wn   = wid & 3;         // 0..3
    const int row0 = blockIdx.y * GBM;
    const int col0 = blockIdx.x * GBN;

    const bf16* gsrc[4] = { Ahi + (size_t)row0 * K, Alo + (size_t)row0 * K,
                            Bhi + (size_t)col0 * K, Blo + (size_t)col0 * K };
    const int KT = K >> 6;

    // per-thread cp.async chunk coords: chunk c = tid + i*256 -> row=c>>3, u=c&7
    auto load_stage = [&](int kt, int s) {
        #pragma unroll
        for (int t = 0; t < 4; t++) {
            const bf16* src = gsrc[t];
            #pragma unroll
            for (int i = 0; i < 4; i++) {
                int c = tid + i * 256;
                int row = c >> 3, u = c & 7;
                uint32_t sa = sb + s * STAGE_B + t * TILE_B + swz(row * 128 + u * 16);
                const bf16* ga = src + (size_t)row * K + kt * 64 + u * 8;
                asm volatile("cp.async.cg.shared.global [%0], [%1], 16;"
                             :: "r"(sa), "l"(ga));
            }
        }
        asm volatile("cp.async.commit_group;" ::: "memory");
    };

    float acc[4][4][4];
    #pragma unroll
    for (int a = 0; a < 4; a++)
        #pragma unroll
        for (int b = 0; b < 4; b++)
            #pragma unroll
            for (int c = 0; c < 4; c++) acc[a][b][c] = 0.f;

    // ldmatrix per-lane address precompute
    const int g  = lane >> 3, lr = lane & 7;
    const int au = g >> 1;                       // A: +16B unit for k8..15 groups
    const int bu = g & 1;                        // B: +16B unit
    uint32_t arow[4], brow[2];
    #pragma unroll
    for (int mt = 0; mt < 4; mt++)
        arow[mt] = (uint32_t)(wm * 64 + mt * 16 + ((g & 1) << 3) + lr) * 128;
    #pragma unroll
    for (int nt = 0; nt < 2; nt++)
        brow[nt] = (uint32_t)(wn * 32 + nt * 16 + ((g >> 1) << 3) + lr) * 128;

    load_stage(0, 0);

    for (int kt = 0; kt < KT; kt++) {
        const int s = kt & 1;
        if (kt + 1 < KT) {
            load_stage(kt + 1, s ^ 1);
            asm volatile("cp.async.wait_group 1;" ::: "memory");
        } else {
            asm volatile("cp.async.wait_group 0;" ::: "memory");
        }
        __syncthreads();

        const uint32_t ab = sb + s * STAGE_B;
        #pragma unroll
        for (int ks = 0; ks < 4; ks++) {
            const uint32_t aun = (uint32_t)(ks * 2 + au) * 16;
            const uint32_t bun = (uint32_t)(ks * 2 + bu) * 16;
            uint32_t bh[2][4], ah[4][4];
            ldsm4(bh[0], ab + 2 * TILE_B + swz(brow[0] + bun));
            ldsm4(bh[1], ab + 2 * TILE_B + swz(brow[1] + bun));
            #pragma unroll
            for (int mt = 0; mt < 4; mt++)
                ldsm4(ah[mt], ab + swz(arow[mt] + aun));
            #pragma unroll
            for (int mt = 0; mt < 4; mt++)
                #pragma unroll
                for (int nt = 0; nt < 2; nt++) {
                    mma16816(acc[mt][nt * 2 + 0], ah[mt], &bh[nt][0]);
                    mma16816(acc[mt][nt * 2 + 1], ah[mt], &bh[nt][2]);
                }
            uint32_t al[4][4];
            #pragma unroll
            for (int mt = 0; mt < 4; mt++)
                ldsm4(al[mt], ab + TILE_B + swz(arow[mt] + aun));
            #pragma unroll
            for (int mt = 0; mt < 4; mt++)
                #pragma unroll
                for (int nt = 0; nt < 2; nt++) {
                    mma16816(acc[mt][nt * 2 + 0], al[mt], &bh[nt][0]);
                    mma16816(acc[mt][nt * 2 + 1], al[mt], &bh[nt][2]);
                }
            uint32_t bl[2][4];
            ldsm4(bl[0], ab + 3 * TILE_B + swz(brow[0] + bun));
            ldsm4(bl[1], ab + 3 * TILE_B + swz(brow[1] + bun));
            #pragma unroll
            for (int mt = 0; mt < 4; mt++)
                #pragma unroll
                for (int nt = 0; nt < 2; nt++) {
                    mma16816(acc[mt][nt * 2 + 0], ah[mt], &bl[nt][0]);
                    mma16816(acc[mt][nt * 2 + 1], ah[mt], &bl[nt][2]);
                }
        }
        __syncthreads();
    }

    // ---------------- epilogue ----------------
    const int rbase = row0 + wm * 64;
    const int cbase = col0 + wn * 32;
    #pragma unroll
    for (int mt = 0; mt < 4; mt++) {
        #pragma unroll
        for (int hh = 0; hh < 2; hh++) {
            int r = rbase + mt * 16 + hh * 8 + (lane >> 2);
            int out_r = remap ? (r + (r >> 10) + 1) : r;
            #pragma unroll
            for (int j = 0; j < 4; j++) {
                int cc = cbase + j * 8 + ((lane & 3) << 1);
                float v0 = acc[mt][j][hh * 2 + 0];
                float v1 = acc[mt][j][hh * 2 + 1];
                if (bias) { v0 += bias[cc]; v1 += bias[cc + 1]; }
                if (Cf) {
                    *reinterpret_cast<float2*>(&Cf[(size_t)out_r * N + cc]) =
                        make_float2(v0, v1);
                }
                if (Chi) {
                    bf16 h0, l0, h1, l1;
                    split1(v0, h0, l0); split1(v1, h1, l1);
                    *reinterpret_cast<__nv_bfloat162*>(&Chi[(size_t)out_r * N + cc]) =
                        __halves2bfloat162(h0, h1);
                    *reinterpret_cast<__nv_bfloat162*>(&Clo[(size_t)out_r * N + cc]) =
                        __halves2bfloat162(l0, l1);
                }
            }
        }
    }
}

// ---------------- flash-style attention (fp32, online softmax) ---------------
// Writes hi/lo bf16 split output for the O-projection GEMM.
#define AQ 64
#define AK 32
#define AD 64
#define QPAD 68
#define SPAD 33

__global__ __launch_bounds__(256)
void attn_kernel(const float* __restrict__ Q, const float* __restrict__ Kt,
                 const float* __restrict__ Vt,
                 bf16* __restrict__ Ohi, bf16* __restrict__ Olo) {
    __shared__ float Qs[AQ][QPAD];
    __shared__ float Ks[AK][QPAD];
    __shared__ float Vs[AK][QPAD];
    __shared__ float Ss[AQ][SPAD];
    __shared__ float mrow[AQ], lrow[AQ], srow[AQ];

    const int qt = blockIdx.x;
    const int bh = blockIdx.y;
    const int b  = bh >> 4;
    const int hd = bh & 15;
    const int q0 = qt * AQ;

    const int tid = threadIdx.x;
    const int tx  = tid & 15;
    const int ty  = tid >> 4;

    for (int e = tid; e < AQ * AD; e += 256) {
        int r = e >> 6, d = e & 63;
        Qs[r][d] = Q[(size_t)(b * T_ + q0 + r) * D_ + hd * HD_ + d];
    }
    if (tid < AQ) { mrow[tid] = -1e30f; lrow[tid] = 0.f; }

    float acc[4][4];
    #pragma unroll
    for (int i = 0; i < 4; i++)
        #pragma unroll
        for (int j = 0; j < 4; j++) acc[i][j] = 0.f;

    const int kmax   = (q0 + AQ - 1) / 3;
    const int ntiles = (kmax + AK) / AK;

    for (int t = 0; t < ntiles; t++) {
        const int kbase = t * AK;
        __syncthreads();
        for (int e = tid; e < AK * AD; e += 256) {
            int r = e >> 6, d = e & 63;
            size_t off = (size_t)(b * TK_ + kbase + r) * D_ + hd * HD_ + d;
            Ks[r][d] = Kt[off];
            Vs[r][d] = Vt[off];
        }
        __syncthreads();

        {
            float s[4][2];
            #pragma unroll
            for (int i = 0; i < 4; i++) { s[i][0] = 0.f; s[i][1] = 0.f; }
            const int c0 = tx * 2;
            #pragma unroll
            for (int d4 = 0; d4 < AD / 4; d4++) {
                float4 kv0 = *reinterpret_cast<const float4*>(&Ks[c0 + 0][d4 * 4]);
                float4 kv1 = *reinterpret_cast<const float4*>(&Ks[c0 + 1][d4 * 4]);
                #pragma unroll
                for (int i = 0; i < 4; i++) {
                    float4 qv = *reinterpret_cast<const float4*>(&Qs[ty * 4 + i][d4 * 4]);
                    s[i][0] += qv.x * kv0.x + qv.y * kv0.y + qv.z * kv0.z + qv.w * kv0.w;
                    s[i][1] += qv.x * kv1.x + qv.y * kv1.y + qv.z * kv1.z + qv.w * kv1.w;
                }
            }
            #pragma unroll
            for (int i = 0; i < 4; i++) {
                int qg = q0 + ty * 4 + i;
                #pragma unroll
                for (int j = 0; j < 2; j++) {
                    int kg = kbase + c0 + j;
                    float v = s[i][j] * 0.125f;
                    if (3 * kg > qg) v = -1e30f;
                    Ss[ty * 4 + i][c0 + j] = v;
                }
            }
        }
        __syncthreads();

        if (tid < AQ) {
            int r = tid;
            float m = mrow[r];
            float mn = m;
            #pragma unroll
            for (int c = 0; c < AK; c++) mn = fmaxf(mn, Ss[r][c]);
            float corr = __expf(m - mn);
            float l = lrow[r] * corr;
            #pragma unroll
            for (int c = 0; c < AK; c++) {
                float p = __expf(Ss[r][c] - mn);
                Ss[r][c] = p;
                l += p;
            }
            mrow[r] = mn; lrow[r] = l; srow[r] = corr;
        }
        __syncthreads();

        #pragma unroll
        for (int i = 0; i < 4; i++) {
            const int r = ty * 4 + i;
            const float corr = srow[r];
            #pragma unroll
            for (int j = 0; j < 4; j++) acc[i][j] *= corr;
            #pragma unroll
            for (int kk = 0; kk < AK; kk++) {
                float p = Ss[r][kk];
                float4 vv = *reinterpret_cast<const float4*>(&Vs[kk][tx * 4]);
                acc[i][0] += p * vv.x;
                acc[i][1] += p * vv.y;
                acc[i][2] += p * vv.z;
                acc[i][3] += p * vv.w;
            }
        }
    }

    #pragma unroll
    for (int i = 0; i < 4; i++) {
        int r = ty * 4 + i;
        float inv = 1.f / lrow[r];
        size_t base = (size_t)(b * T_ + q0 + r) * D_ + hd * HD_ + tx * 4;
        float v0 = acc[i][0] * inv, v1 = acc[i][1] * inv;
        float v2 = acc[i][2] * inv, v3 = acc[i][3] * inv;
        bf16 h0, l0, h1, l1, h2, l2, h3, l3;
        split1(v0, h0, l0); split1(v1, h1, l1);
        split1(v2, h2, l2); split1(v3, h3, l3);
        *reinterpret_cast<__nv_bfloat162*>(&Ohi[base + 0]) = __halves2bfloat162(h0, h1);
        *reinterpret_cast<__nv_bfloat162*>(&Ohi[base + 2]) = __halves2bfloat162(h2, h3);
        *reinterpret_cast<__nv_bfloat162*>(&Olo[base + 0]) = __halves2bfloat162(l0, l1);
        *reinterpret_cast<__nv_bfloat162*>(&Olo[base + 2]) = __halves2bfloat162(l2, l3);
    }
}

// ---------------- launch ------------------------------------------------------
extern "C" void kernel_launch(void* const* d_in, const int* in_sizes, int n_in,
                              void* d_out, int out_size) {
    const float* x     = (const float*)d_in[0];
    const float* Wq    = (const float*)d_in[1];
    const float* Wk    = (const float*)d_in[2];
    const float* Wv    = (const float*)d_in[3];
    const float* Wo    = (const float*)d_in[4];
    const float* bo    = (const float*)d_in[5];
    const float* Wconv = (const float*)d_in[6];
    float* out = (float*)d_out;

    bf16 *xhi, *xlo, *Wc2hi, *Wc2lo, *Wqhi, *Wqlo, *Wkhi, *Wklo;
    bf16 *Wvhi, *Wvlo, *Wohi, *Wolo, *kthi, *ktlo, *athi, *atlo;
    float *kf, *vf, *qf;
    cudaGetSymbolAddress((void**)&xhi,  g_xhi);  cudaGetSymbolAddress((void**)&xlo,  g_xlo);
    cudaGetSymbolAddress((void**)&Wc2hi,g_Wc2hi);cudaGetSymbolAddress((void**)&Wc2lo,g_Wc2lo);
    cudaGetSymbolAddress((void**)&Wqhi, g_Wqhi); cudaGetSymbolAddress((void**)&Wqlo, g_Wqlo);
    cudaGetSymbolAddress((void**)&Wkhi, g_Wkhi); cudaGetSymbolAddress((void**)&Wklo, g_Wklo);
    cudaGetSymbolAddress((void**)&Wvhi, g_Wvhi); cudaGetSymbolAddress((void**)&Wvlo, g_Wvlo);
    cudaGetSymbolAddress((void**)&Wohi, g_Wohi); cudaGetSymbolAddress((void**)&Wolo, g_Wolo);
    cudaGetSymbolAddress((void**)&kthi, g_kthi); cudaGetSymbolAddress((void**)&ktlo, g_ktlo);
    cudaGetSymbolAddress((void**)&athi, g_athi); cudaGetSymbolAddress((void**)&atlo, g_atlo);
    cudaGetSymbolAddress((void**)&kf, g_k);
    cudaGetSymbolAddress((void**)&vf, g_v);
    cudaGetSymbolAddress((void**)&qf, g_q);

    cudaFuncSetAttribute(gemm_hmma, cudaFuncAttributeMaxDynamicSharedMemorySize, GSMEM);

    // pre-pass splits
    split_ker<<<(MQ_ * D_ / 4 + 255) / 256, 256>>>(x,  xhi,  xlo,  MQ_ * D_ / 4);
    split_ker<<<(D_ * D_ / 4 + 255) / 256, 256>>>(Wq, Wqhi, Wqlo, D_ * D_ / 4);
    split_ker<<<(D_ * D_ / 4 + 255) / 256, 256>>>(Wk, Wkhi, Wklo, D_ * D_ / 4);
    split_ker<<<(D_ * D_ / 4 + 255) / 256, 256>>>(Wv, Wvhi, Wvlo, D_ * D_ / 4);
    split_ker<<<(D_ * D_ / 4 + 255) / 256, 256>>>(Wo, Wohi, Wolo, D_ * D_ / 4);
    prep_conv<<<(D_ * 3 * D_ + 255) / 256, 256>>>(Wconv, x, Wc2hi, Wc2lo, kthi, ktlo);

    // conv pooling GEMM: (4096, 3072) -> k_tmp hi/lo (remapped rows)
    gemm_hmma<<<dim3(D_ / GBN, 4096 / GBM), 256, GSMEM>>>(
        xhi, xlo, Wc2hi, Wc2lo, nullptr, kthi, ktlo, nullptr, 4096, D_, 3 * D_, 1);
    // K / V projections -> fp32
    gemm_hmma<<<dim3(D_ / GBN, TKPAD / GBM), 256, GSMEM>>>(
        kthi, ktlo, Wkhi, Wklo, kf, nullptr, nullptr, nullptr, TKPAD, D_, D_, 0);
    gemm_hmma<<<dim3(D_ / GBN, TKPAD / GBM), 256, GSMEM>>>(
        kthi, ktlo, Wvhi, Wvlo, vf, nullptr, nullptr, nullptr, TKPAD, D_, D_, 0);
    // Q projection -> fp32
    gemm_hmma<<<dim3(D_ / GBN, MQ_ / GBM), 256, GSMEM>>>(
        xhi, xlo, Wqhi, Wqlo, qf, nullptr, nullptr, nullptr, MQ_, D_, D_, 0);
    // attention (fp32) -> hi/lo split output
    attn_kernel<<<dim3(T_ / AQ, B_ * H_), 256>>>(qf, kf, vf, athi, atlo);
    // output projection + bias -> d_out
    gemm_hmma<<<dim3(D_ / GBN, MQ_ / GBM), 256, GSMEM>>>(
        athi, atlo, Wohi, Wolo, out, nullptr, nullptr, bo, MQ_, D_, D_, 0);
}

// round 10
// speedup vs baseline: 2.9660x; 1.5516x over previous
#include <cuda_runtime.h>
#include <cuda_bf16.h>
#include <cstdint>

// Problem constants
#define B_   4
#define T_   3072
#define D_   1024
#define H_   16
#define HD_  64
#define TK_  1025
#define TKPAD 4224
#define MQ_  (B_ * T_)
#define TKP2 1088              // padded key length for vT rows

typedef __nv_bfloat16 bf16;

// ---------------- scratch (static device globals) ----------------------------
__device__ bf16  g_xhi [MQ_ * D_],  g_xlo [MQ_ * D_];
__device__ bf16  g_Wc2hi[D_ * 3 * D_], g_Wc2lo[D_ * 3 * D_];
__device__ bf16  g_Wqhi[D_ * D_], g_Wqlo[D_ * D_];
__device__ bf16  g_Wkhi[D_ * D_], g_Wklo[D_ * D_];
__device__ bf16  g_Wvhi[D_ * D_], g_Wvlo[D_ * D_];
__device__ bf16  g_Wohi[D_ * D_], g_Wolo[D_ * D_];
__device__ bf16  g_kthi[TKPAD * D_], g_ktlo[TKPAD * D_];
__device__ bf16  g_qhi [MQ_ * D_],  g_qlo [MQ_ * D_];
__device__ bf16  g_khi [TKPAD * D_], g_klo [TKPAD * D_];
__device__ bf16  g_vthi[B_ * H_ * HD_ * TKP2], g_vtlo[B_ * H_ * HD_ * TKP2];
__device__ bf16  g_athi[MQ_ * D_],  g_atlo[MQ_ * D_];

// ---------------- helpers ----------------------------------------------------
__device__ __forceinline__ uint32_t smem_u32(const void* p) {
    uint32_t a;
    asm("{ .reg .u64 t; cvta.to.shared.u64 t, %1; cvt.u32.u64 %0, t; }"
        : "=r"(a) : "l"(p));
    return a;
}
__device__ __forceinline__ uint32_t swz(uint32_t o) {   // SW128 swizzle
    return o ^ ((o >> 3) & 0x70);
}
__device__ __forceinline__ void split1(float v, bf16& h, bf16& l) {
    h = __float2bfloat16(v);
    l = __float2bfloat16(v - __bfloat162float(h));
}
__device__ __forceinline__ uint32_t pack2(bf16 a, bf16 b) {
    __nv_bfloat162 t = __halves2bfloat162(a, b);
    return *reinterpret_cast<uint32_t*>(&t);
}
__device__ __forceinline__ void ldsm4(uint32_t* r, uint32_t a) {
    asm volatile("ldmatrix.sync.aligned.m8n8.x4.shared.b16 {%0,%1,%2,%3}, [%4];"
                 : "=r"(r[0]), "=r"(r[1]), "=r"(r[2]), "=r"(r[3]) : "r"(a));
}
__device__ __forceinline__ void mma16816(float* c, const uint32_t* a, const uint32_t* b) {
    asm volatile(
        "mma.sync.aligned.m16n8k16.row.col.f32.bf16.bf16.f32 "
        "{%0,%1,%2,%3}, {%4,%5,%6,%7}, {%8,%9}, {%0,%1,%2,%3};"
        : "+f"(c[0]), "+f"(c[1]), "+f"(c[2]), "+f"(c[3])
        : "r"(a[0]), "r"(a[1]), "r"(a[2]), "r"(a[3]), "r"(b[0]), "r"(b[1]));
}
#define CPASYNC16(dst, src) \
    asm volatile("cp.async.cg.shared.global [%0], [%1], 16;" :: "r"(dst), "l"(src))
#define CPCOMMIT() asm volatile("cp.async.commit_group;" ::: "memory")
#define CPWAIT(n)  asm volatile("cp.async.wait_group %0;" :: "n"(n) : "memory")

// ---------------- pre-pass: elementwise fp32 -> bf16 hi/lo -------------------
__global__ void split_ker(const float* __restrict__ s,
                          bf16* __restrict__ hi, bf16* __restrict__ lo, int n4) {
    int i = blockIdx.x * blockDim.x + threadIdx.x;
    if (i >= n4) return;
    float4 v = reinterpret_cast<const float4*>(s)[i];
    bf16 h0, h1, h2, h3, l0, l1, l2, l3;
    split1(v.x, h0, l0); split1(v.y, h1, l1);
    split1(v.z, h2, l2); split1(v.w, h3, l3);
    reinterpret_cast<uint32_t*>(hi)[i * 2 + 0] = pack2(h0, h1);
    reinterpret_cast<uint32_t*>(hi)[i * 2 + 1] = pack2(h2, h3);
    reinterpret_cast<uint32_t*>(lo)[i * 2 + 0] = pack2(l0, l1);
    reinterpret_cast<uint32_t*>(lo)[i * 2 + 1] = pack2(l2, l3);
}

// permute Wconv (O,I,KW)->(O,KW,I) + split; seed k_tmp row0/batch; zero pad rows
__global__ void prep_conv(const float* __restrict__ Wconv,
                          const float* __restrict__ x,
                          bf16* __restrict__ Wc2hi, bf16* __restrict__ Wc2lo,
                          bf16* __restrict__ kthi,  bf16* __restrict__ ktlo) {
    int idx = blockIdx.x * blockDim.x + threadIdx.x;
    if (idx < D_ * 3 * D_) {
        int o   = idx / (3 * D_);
        int rem = idx - o * (3 * D_);
        int kw  = rem >> 10;
        int i   = rem & (D_ - 1);
        float v = Wconv[(size_t)o * 3 * D_ + i * 3 + kw];
        bf16 h, l; split1(v, h, l);
        Wc2hi[idx] = h; Wc2lo[idx] = l;
    }
    if (idx < B_ * D_) {
        int b = idx >> 10, d = idx & (D_ - 1);
        float v = x[(size_t)(b * T_) * D_ + d];
        bf16 h, l; split1(v, h, l);
        kthi[(size_t)(b * TK_) * D_ + d] = h;
        ktlo[(size_t)(b * TK_) * D_ + d] = l;
    }
    if (idx < (TKPAD - B_ * TK_) * D_) {
        size_t off = (size_t)(B_ * TK_) * D_ + idx;
        kthi[off] = __float2bfloat16(0.f);
        ktlo[off] = __float2bfloat16(0.f);
    }
}

// ---------------- HMMA split-bf16 GEMM: C = A @ W^T --------------------------
// Block 128x128x64, 256 thr (8 warps 2x4), cp.async 3-stage pipeline.
// mode: 0 = fp32 out (+bias), 1 = bf16 hi/lo natural, 2 = mode1 + conv remap,
//       3 = bf16 hi/lo transposed per-(b,h) vT[bh][hd][t]
#define GBM 128
#define GBN 128
#define TILE_B 16384
#define STAGE_B (4 * TILE_B)
#define GSMEM (3 * STAGE_B)      // 192 KB

__global__ __launch_bounds__(256, 1)
void gemm_hmma(const bf16* __restrict__ Ahi, const bf16* __restrict__ Alo,
               const bf16* __restrict__ Bhi, const bf16* __restrict__ Blo,
               float* __restrict__ Cf, bf16* __restrict__ Chi, bf16* __restrict__ Clo,
               const float* __restrict__ bias, int M, int N, int K, int mode) {
    extern __shared__ char smem[];
    const uint32_t sb = smem_u32(smem);
    const int tid  = threadIdx.x;
    const int lane = tid & 31;
    const int wid  = tid >> 5;
    const int wm   = wid >> 2;
    const int wn   = wid & 3;
    const int row0 = blockIdx.y * GBM;
    const int col0 = blockIdx.x * GBN;

    const bf16* gsrc[4] = { Ahi + (size_t)row0 * K, Alo + (size_t)row0 * K,
                            Bhi + (size_t)col0 * K, Blo + (size_t)col0 * K };
    const int KT = K >> 6;

    auto load_stage = [&](int kt, int s) {
        #pragma unroll
        for (int t = 0; t < 4; t++) {
            const bf16* src = gsrc[t];
            #pragma unroll
            for (int i = 0; i < 4; i++) {
                int c = tid + i * 256;
                int row = c >> 3, u = c & 7;
                uint32_t sa = sb + s * STAGE_B + t * TILE_B + swz(row * 128 + u * 16);
                const bf16* ga = src + (size_t)row * K + kt * 64 + u * 8;
                CPASYNC16(sa, ga);
            }
        }
        CPCOMMIT();
    };

    float acc[4][4][4];
    #pragma unroll
    for (int a = 0; a < 4; a++)
        #pragma unroll
        for (int b = 0; b < 4; b++)
            #pragma unroll
            for (int c = 0; c < 4; c++) acc[a][b][c] = 0.f;

    const int g  = lane >> 3, lr = lane & 7;
    const int au = g >> 1;
    const int bu = g & 1;
    uint32_t arow[4], brow[2];
    #pragma unroll
    for (int mt = 0; mt < 4; mt++)
        arow[mt] = (uint32_t)(wm * 64 + mt * 16 + ((g & 1) << 3) + lr) * 128;
    #pragma unroll
    for (int nt = 0; nt < 2; nt++)
        brow[nt] = (uint32_t)(wn * 32 + nt * 16 + ((g >> 1) << 3) + lr) * 128;

    load_stage(0, 0);
    if (KT > 1) load_stage(1, 1);

    for (int kt = 0; kt < KT; kt++) {
        if (kt + 1 < KT) { CPWAIT(1); } else { CPWAIT(0); }   // drain own stage on last iter
        __syncthreads();
        if (kt + 2 < KT) load_stage(kt + 2, (kt + 2) % 3);

        const uint32_t ab = sb + (kt % 3) * STAGE_B;
        #pragma unroll
        for (int ks = 0; ks < 4; ks++) {
            const uint32_t aun = (uint32_t)(ks * 2 + au) * 16;
            const uint32_t bun = (uint32_t)(ks * 2 + bu) * 16;
            uint32_t bh[2][4], ah[4][4];
            ldsm4(bh[0], ab + 2 * TILE_B + swz(brow[0] + bun));
            ldsm4(bh[1], ab + 2 * TILE_B + swz(brow[1] + bun));
            #pragma unroll
            for (int mt = 0; mt < 4; mt++)
                ldsm4(ah[mt], ab + swz(arow[mt] + aun));
            #pragma unroll
            for (int mt = 0; mt < 4; mt++)
                #pragma unroll
                for (int nt = 0; nt < 2; nt++) {
                    mma16816(acc[mt][nt * 2 + 0], ah[mt], &bh[nt][0]);
                    mma16816(acc[mt][nt * 2 + 1], ah[mt], &bh[nt][2]);
                }
            uint32_t al[4][4];
            #pragma unroll
            for (int mt = 0; mt < 4; mt++)
                ldsm4(al[mt], ab + TILE_B + swz(arow[mt] + aun));
            #pragma unroll
            for (int mt = 0; mt < 4; mt++)
                #pragma unroll
                for (int nt = 0; nt < 2; nt++) {
                    mma16816(acc[mt][nt * 2 + 0], al[mt], &bh[nt][0]);
                    mma16816(acc[mt][nt * 2 + 1], al[mt], &bh[nt][2]);
                }
            uint32_t bl[2][4];
            ldsm4(bl[0], ab + 3 * TILE_B + swz(brow[0] + bun));
            ldsm4(bl[1], ab + 3 * TILE_B + swz(brow[1] + bun));
            #pragma unroll
            for (int mt = 0; mt < 4; mt++)
                #pragma unroll
                for (int nt = 0; nt < 2; nt++) {
                    mma16816(acc[mt][nt * 2 + 0], ah[mt], &bl[nt][0]);
                    mma16816(acc[mt][nt * 2 + 1], ah[mt], &bl[nt][2]);
                }
        }
        __syncthreads();
    }

    // ---------------- epilogue ----------------
    const int rbase = row0 + wm * 64;
    const int cbase = col0 + wn * 32;
    #pragma unroll
    for (int mt = 0; mt < 4; mt++) {
        #pragma unroll
        for (int hh = 0; hh < 2; hh++) {
            int r = rbase + mt * 16 + hh * 8 + (lane >> 2);
            int out_r = (mode == 2) ? (r + (r >> 10) + 1) : r;
            #pragma unroll
            for (int j = 0; j < 4; j++) {
                int cc = cbase + j * 8 + ((lane & 3) << 1);
                float v0 = acc[mt][j][hh * 2 + 0];
                float v1 = acc[mt][j][hh * 2 + 1];
                if (mode == 0) {
                    if (bias) { v0 += bias[cc]; v1 += bias[cc + 1]; }
                    *reinterpret_cast<float2*>(&Cf[(size_t)out_r * N + cc]) =
                        make_float2(v0, v1);
                } else if (mode == 3) {
                    if (r < B_ * TK_) {
                        int bb = r / TK_;
                        int t  = r - bb * TK_;
                        int hq = cc >> 6, hd0 = cc & 63;
                        size_t base = ((size_t)(bb * H_ + hq) * HD_);
                        bf16 h0, l0, h1, l1;
                        split1(v0, h0, l0); split1(v1, h1, l1);
                        Chi[(base + hd0)     * TKP2 + t] = h0;
                        Chi[(base + hd0 + 1) * TKP2 + t] = h1;
                        Clo[(base + hd0)     * TKP2 + t] = l0;
                        Clo[(base + hd0 + 1) * TKP2 + t] = l1;
                    }
                } else {
                    bf16 h0, l0, h1, l1;
                    split1(v0, h0, l0); split1(v1, h1, l1);
                    *reinterpret_cast<uint32_t*>(&Chi[(size_t)out_r * N + cc]) =
                        pack2(h0, h1);
                    *reinterpret_cast<uint32_t*>(&Clo[(size_t)out_r * N + cc]) =
                        pack2(l0, l1);
                }
            }
        }
    }
}

// ---------------- HMMA flash attention ---------------------------------------
// Block: 64 q-rows; tiles of 64 keys; 256 thr = 8 warps in 4x2 (m16 x n32).
// smem offsets (bytes)
#define A_QHI 0
#define A_QLO 8192
#define A_KV0 16384            // + stage*32768: KHI,KLO,VHI,VLO (8KB each)
#define A_PHI 81920
#define A_PLO 90112
#define A_SS  98304            // float[64][68]
#define A_MR  (A_SS + 17408)
#define A_LR  (A_MR + 256)
#define A_SR  (A_LR + 256)
#define ASMEM (A_SR + 256)     // 116736 B

__global__ __launch_bounds__(256, 1)
void attn_hmma(const bf16* __restrict__ qhi, const bf16* __restrict__ qlo,
               const bf16* __restrict__ khi, const bf16* __restrict__ klo,
               const bf16* __restrict__ vthi, const bf16* __restrict__ vtlo,
               bf16* __restrict__ ohi, bf16* __restrict__ olo) {
    extern __shared__ char sm[];
    const uint32_t sb = smem_u32(sm);
    const int tid = threadIdx.x, lane = tid & 31, wid = tid >> 5;
    const int g = lane >> 3, lr = lane & 7;
    const int wm = wid >> 1, wn = wid & 1;
    const int qt = blockIdx.x, bh = blockIdx.y, b = bh >> 4, h = bh & 15;
    const int q0 = qt * 64;

    float* Sp  = reinterpret_cast<float*>(sm + A_SS);
    float* mr  = reinterpret_cast<float*>(sm + A_MR);
    float* lrw = reinterpret_cast<float*>(sm + A_LR);
    float* srw = reinterpret_cast<float*>(sm + A_SR);
    if (tid < 64) { mr[tid] = -1e30f; lrw[tid] = 0.f; }

    auto load_kv = [&](int t, int s) {
        const uint32_t kvb = sb + A_KV0 + s * 32768;
        const int kb = t * 64;
        #pragma unroll
        for (int i = 0; i < 2; i++) {
            int c = tid + i * 256, row = c >> 3, u = c & 7;
            uint32_t so = swz(row * 128 + u * 16);
            size_t koff = (size_t)(b * TK_ + kb + row) * D_ + h * 64 + u * 8;
            size_t voff = ((size_t)bh * HD_ + row) * TKP2 + kb + u * 8;
            CPASYNC16(kvb + so,             khi + koff);
            CPASYNC16(kvb + 8192 + so,      klo + koff);
            CPASYNC16(kvb + 16384 + so,     vthi + voff);
            CPASYNC16(kvb + 24576 + so,     vtlo + voff);
        }
    };

    // group0: Q hi/lo + KV tile 0
    {
        #pragma unroll
        for (int t2 = 0; t2 < 2; t2++) {
            const bf16* qs = t2 ? qlo : qhi;
            #pragma unroll
            for (int i = 0; i < 2; i++) {
                int c = tid + i * 256, row = c >> 3, u = c & 7;
                uint32_t da = sb + A_QHI + t2 * 8192 + swz(row * 128 + u * 16);
                CPASYNC16(da, qs + (size_t)(b * T_ + q0 + row) * D_ + h * 64 + u * 8);
            }
        }
        load_kv(0, 0);
        CPCOMMIT();
    }

    const uint32_t arow  = (uint32_t)(wm * 16 + ((g & 1) << 3) + lr) * 128;
    const uint32_t brow0 = (uint32_t)(wn * 32 + ((g >> 1) << 3) + lr) * 128;
    const uint32_t brow1 = brow0 + 16 * 128;
    const int au = g >> 1, bu = g & 1;

    float pacc[4][4];
    #pragma unroll
    for (int j = 0; j < 4; j++)
        #pragma unroll
        for (int c = 0; c < 4; c++) pacc[j][c] = 0.f;

    const int nt = (q0 + 63) / 3 / 64 + 1;

    for (int t = 0; t < nt; t++) {
        __syncthreads();                 // all done with PV of t-1 (buffer reuse)
        if (t + 1 < nt) {
            load_kv(t + 1, (t + 1) & 1); CPCOMMIT();
            CPWAIT(1);                   // current tile (prev group) complete
        } else {
            CPWAIT(0);                   // LAST tile: drain our own group too
        }
        __syncthreads();

        const uint32_t kvb = sb + A_KV0 + (t & 1) * 32768;
        const int kbase = t * 64;

        // ---- S = Q @ K^T (3-term split) ----
        float sacc[4][4];
        #pragma unroll
        for (int j = 0; j < 4; j++)
            #pragma unroll
            for (int c = 0; c < 4; c++) sacc[j][c] = 0.f;
        #pragma unroll
        for (int ks = 0; ks < 4; ks++) {
            const uint32_t aun = (uint32_t)(ks * 2 + au) * 16;
            const uint32_t bun = (uint32_t)(ks * 2 + bu) * 16;
            uint32_t ah[4], al[4], kh0[4], kh1[4], kl0[4], kl1[4];
            ldsm4(ah, sb + A_QHI + swz(arow + aun));
            ldsm4(kh0, kvb + swz(brow0 + bun));
            ldsm4(kh1, kvb + swz(brow1 + bun));
            mma16816(sacc[0], ah, &kh0[0]); mma16816(sacc[1], ah, &kh0[2]);
            mma16816(sacc[2], ah, &kh1[0]); mma16816(sacc[3], ah, &kh1[2]);
            ldsm4(al, sb + A_QLO + swz(arow + aun));
            mma16816(sacc[0], al, &kh0[0]); mma16816(sacc[1], al, &kh0[2]);
            mma16816(sacc[2], al, &kh1[0]); mma16816(sacc[3], al, &kh1[2]);
            ldsm4(kl0, kvb + 8192 + swz(brow0 + bun));
            ldsm4(kl1, kvb + 8192 + swz(brow1 + bun));
            mma16816(sacc[0], ah, &kl0[0]); mma16816(sacc[1], ah, &kl0[2]);
            mma16816(sacc[2], ah, &kl1[0]); mma16816(sacc[3], ah, &kl1[2]);
        }
        // scale + mask + stage to smem
        #pragma unroll
        for (int j = 0; j < 4; j++)
            #pragma unroll
            for (int c = 0; c < 4; c++) {
                int row = wm * 16 + ((c >> 1) << 3) + (lane >> 2);
                int col = wn * 32 + j * 8 + ((lane & 3) << 1) + (c & 1);
                float v = sacc[j][c] * 0.125f;
                if (3 * (kbase + col) > q0 + row) v = -1e30f;
                Sp[row * 68 + col] = v;
            }
        __syncthreads();

        // ---- online softmax: 4 threads per row, 16 cols each ----
        {
            const int r = tid >> 2, gq = tid & 3;
            const float* rowp = Sp + r * 68 + gq * 16;
            float pv[16];
            #pragma unroll
            for (int i = 0; i < 4; i++) {
                float4 v = *reinterpret_cast<const float4*>(rowp + i * 4);
                pv[i * 4 + 0] = v.x; pv[i * 4 + 1] = v.y;
                pv[i * 4 + 2] = v.z; pv[i * 4 + 3] = v.w;
            }
            float mold = mr[r];
            float mx = mold;
            #pragma unroll
            for (int i = 0; i < 16; i++) mx = fmaxf(mx, pv[i]);
            mx = fmaxf(mx, __shfl_xor_sync(0xffffffffu, mx, 1));
            mx = fmaxf(mx, __shfl_xor_sync(0xffffffffu, mx, 2));
            float sum = 0.f;
            uint32_t hw[8], lw[8];
            #pragma unroll
            for (int i = 0; i < 8; i++) {
                float p0 = __expf(pv[2 * i + 0] - mx);
                float p1 = __expf(pv[2 * i + 1] - mx);
                sum += p0 + p1;
                bf16 h0, l0, h1, l1;
                split1(p0, h0, l0); split1(p1, h1, l1);
                hw[i] = pack2(h0, h1); lw[i] = pack2(l0, l1);
            }
            sum += __shfl_xor_sync(0xffffffffu, sum, 1);
            sum += __shfl_xor_sync(0xffffffffu, sum, 2);
            uint32_t base = (uint32_t)(r * 128 + gq * 32);
            *reinterpret_cast<uint4*>(sm + A_PHI + swz(base)) =
                make_uint4(hw[0], hw[1], hw[2], hw[3]);
            *reinterpret_cast<uint4*>(sm + A_PHI + swz(base + 16)) =
                make_uint4(hw[4], hw[5], hw[6], hw[7]);
            *reinterpret_cast<uint4*>(sm + A_PLO + swz(base)) =
                make_uint4(lw[0], lw[1], lw[2], lw[3]);
            *reinterpret_cast<uint4*>(sm + A_PLO + swz(base + 16)) =
                make_uint4(lw[4], lw[5], lw[6], lw[7]);
            if (gq == 0) {
                float corr = __expf(mold - mx);
                mr[r] = mx;
                lrw[r] = lrw[r] * corr + sum;
                srw[r] = corr;
            }
        }
        __syncthreads();

        // ---- O = O*corr + P @ V (3-term split) ----
        {
            float s0 = srw[wm * 16 + (lane >> 2)];
            float s1 = srw[wm * 16 + 8 + (lane >> 2)];
            #pragma unroll
            for (int j = 0; j < 4; j++) {
                pacc[j][0] *= s0; pacc[j][1] *= s0;
                pacc[j][2] *= s1; pacc[j][3] *= s1;
            }
            #pragma unroll
            for (int ks = 0; ks < 4; ks++) {
                const uint32_t aun = (uint32_t)(ks * 2 + au) * 16;
                const uint32_t bun = (uint32_t)(ks * 2 + bu) * 16;
                uint32_t ph[4], pl[4], vh0[4], vh1[4], vl0[4], vl1[4];
                ldsm4(ph, sb + A_PHI + swz(arow + aun));
                ldsm4(vh0, kvb + 16384 + swz(brow0 + bun));
                ldsm4(vh1, kvb + 16384 + swz(brow1 + bun));
                mma16816(pacc[0], ph, &vh0[0]); mma16816(pacc[1], ph, &vh0[2]);
                mma16816(pacc[2], ph, &vh1[0]); mma16816(pacc[3], ph, &vh1[2]);
                ldsm4(pl, sb + A_PLO + swz(arow + aun));
                mma16816(pacc[0], pl, &vh0[0]); mma16816(pacc[1], pl, &vh0[2]);
                mma16816(pacc[2], pl, &vh1[0]); mma16816(pacc[3], pl, &vh1[2]);
                ldsm4(vl0, kvb + 24576 + swz(brow0 + bun));
                ldsm4(vl1, kvb + 24576 + swz(brow1 + bun));
                mma16816(pacc[0], ph, &vl0[0]); mma16816(pacc[1], ph, &vl0[2]);
                mma16816(pacc[2], ph, &vl1[0]); mma16816(pacc[3], ph, &vl1[2]);
            }
        }
    }

    // finalize: divide by l, split-write output
    {
        float inv0 = 1.f / lrw[wm * 16 + (lane >> 2)];
        float inv1 = 1.f / lrw[wm * 16 + 8 + (lane >> 2)];
        #pragma unroll
        for (int j = 0; j < 4; j++) {
            #pragma unroll
            for (int cp = 0; cp < 2; cp++) {
                int row = wm * 16 + cp * 8 + (lane >> 2);
                int col = wn * 32 + j * 8 + ((lane & 3) << 1);
                float inv = cp ? inv1 : inv0;
                float v0 = pacc[j][cp * 2 + 0] * inv;
                float v1 = pacc[j][cp * 2 + 1] * inv;
                bf16 h0, l0, h1, l1;
                split1(v0, h0, l0); split1(v1, h1, l1);
                size_t off = (size_t)(b * T_ + q0 + row) * D_ + h * 64 + col;
                *reinterpret_cast<uint32_t*>(&ohi[off]) = pack2(h0, h1);
                *reinterpret_cast<uint32_t*>(&olo[off]) = pack2(l0, l1);
            }
        }
    }
}

// ---------------- launch ------------------------------------------------------
extern "C" void kernel_launch(void* const* d_in, const int* in_sizes, int n_in,
                              void* d_out, int out_size) {
    const float* x     = (const float*)d_in[0];
    const float* Wq    = (const float*)d_in[1];
    const float* Wk    = (const float*)d_in[2];
    const float* Wv    = (const float*)d_in[3];
    const float* Wo    = (const float*)d_in[4];
    const float* bo    = (const float*)d_in[5];
    const float* Wconv = (const float*)d_in[6];
    float* out = (float*)d_out;

    bf16 *xhi, *xlo, *Wc2hi, *Wc2lo, *Wqhi, *Wqlo, *Wkhi, *Wklo;
    bf16 *Wvhi, *Wvlo, *Wohi, *Wolo, *kthi, *ktlo, *athi, *atlo;
    bf16 *qhi, *qlo, *khi, *klo, *vthi, *vtlo;
    cudaGetSymbolAddress((void**)&xhi,  g_xhi);  cudaGetSymbolAddress((void**)&xlo,  g_xlo);
    cudaGetSymbolAddress((void**)&Wc2hi,g_Wc2hi);cudaGetSymbolAddress((void**)&Wc2lo,g_Wc2lo);
    cudaGetSymbolAddress((void**)&Wqhi, g_Wqhi); cudaGetSymbolAddress((void**)&Wqlo, g_Wqlo);
    cudaGetSymbolAddress((void**)&Wkhi, g_Wkhi); cudaGetSymbolAddress((void**)&Wklo, g_Wklo);
    cudaGetSymbolAddress((void**)&Wvhi, g_Wvhi); cudaGetSymbolAddress((void**)&Wvlo, g_Wvlo);
    cudaGetSymbolAddress((void**)&Wohi, g_Wohi); cudaGetSymbolAddress((void**)&Wolo, g_Wolo);
    cudaGetSymbolAddress((void**)&kthi, g_kthi); cudaGetSymbolAddress((void**)&ktlo, g_ktlo);
    cudaGetSymbolAddress((void**)&athi, g_athi); cudaGetSymbolAddress((void**)&atlo, g_atlo);
    cudaGetSymbolAddress((void**)&qhi,  g_qhi);  cudaGetSymbolAddress((void**)&qlo,  g_qlo);
    cudaGetSymbolAddress((void**)&khi,  g_khi);  cudaGetSymbolAddress((void**)&klo,  g_klo);
    cudaGetSymbolAddress((void**)&vthi, g_vthi); cudaGetSymbolAddress((void**)&vtlo, g_vtlo);

    cudaFuncSetAttribute(gemm_hmma, cudaFuncAttributeMaxDynamicSharedMemorySize, GSMEM);
    cudaFuncSetAttribute(attn_hmma, cudaFuncAttributeMaxDynamicSharedMemorySize, ASMEM);

    // pre-pass splits
    split_ker<<<(MQ_ * D_ / 4 + 255) / 256, 256>>>(x,  xhi,  xlo,  MQ_ * D_ / 4);
    split_ker<<<(D_ * D_ / 4 + 255) / 256, 256>>>(Wq, Wqhi, Wqlo, D_ * D_ / 4);
    split_ker<<<(D_ * D_ / 4 + 255) / 256, 256>>>(Wk, Wkhi, Wklo, D_ * D_ / 4);
    split_ker<<<(D_ * D_ / 4 + 255) / 256, 256>>>(Wv, Wvhi, Wvlo, D_ * D_ / 4);
    split_ker<<<(D_ * D_ / 4 + 255) / 256, 256>>>(Wo, Wohi, Wolo, D_ * D_ / 4);
    prep_conv<<<(D_ * 3 * D_ + 255) / 256, 256>>>(Wconv, x, Wc2hi, Wc2lo, kthi, ktlo);

    // conv pooling GEMM -> k_tmp hi/lo (remap)
    gemm_hmma<<<dim3(D_ / GBN, 4096 / GBM), 256, GSMEM>>>(
        xhi, xlo, Wc2hi, Wc2lo, nullptr, kthi, ktlo, nullptr, 4096, D_, 3 * D_, 2);
    // K projection -> k hi/lo (natural)
    gemm_hmma<<<dim3(D_ / GBN, TKPAD / GBM), 256, GSMEM>>>(
        kthi, ktlo, Wkhi, Wklo, nullptr, khi, klo, nullptr, TKPAD, D_, D_, 1);
    // V projection -> vT hi/lo (transposed per (b,h))
    gemm_hmma<<<dim3(D_ / GBN, TKPAD / GBM), 256, GSMEM>>>(
        kthi, ktlo, Wvhi, Wvlo, nullptr, vthi, vtlo, nullptr, TKPAD, D_, D_, 3);
    // Q projection -> q hi/lo
    gemm_hmma<<<dim3(D_ / GBN, MQ_ / GBM), 256, GSMEM>>>(
        xhi, xlo, Wqhi, Wqlo, nullptr, qhi, qlo, nullptr, MQ_, D_, D_, 1);
    // attention (HMMA) -> attn hi/lo
    attn_hmma<<<dim3(T_ / 64, B_ * H_), 256, ASMEM>>>(
        qhi, qlo, khi, klo, vthi, vtlo, athi, atlo);
    // output projection + bias -> d_out (fp32)
    gemm_hmma<<<dim3(D_ / GBN, MQ_ / GBM), 256, GSMEM>>>(
        athi, atlo, Wohi, Wolo, out, nullptr, nullptr, bo, MQ_, D_, D_, 0);
}